// round 9
// baseline (speedup 1.0000x reference)
#include <cuda_runtime.h>

#define NN 4096
#define NV (NN/4)
#define RPB 8

// ping-pong iteration vectors
__device__ float g_x[2][NN];

// Independent real_T_tilde stream: outR = 0.99*rtt + prev_b (x) curr_b.
// Launched FIRST with 512 resident blocks; stores are WRITE-THROUGH so the
// 64MB output never occupies L2 as dirty lines -> J stays L2-resident for
// the concurrently-running warm matvecs.
__global__ void __launch_bounds__(256) k_rtt(const float* __restrict__ rtt,
                                             const int* __restrict__ prev,
                                             const int* __restrict__ curr,
                                             float* __restrict__ outR) {
    cudaTriggerProgrammaticLaunchCompletion();
    int rowbase = blockIdx.x * 8;
    const int4* Cr = reinterpret_cast<const int4*>(curr);
    #pragma unroll 2
    for (int r = 0; r < 8; r++) {
        int row = rowbase + r;
        float pb = (prev[row] > 0) ? 1.f : 0.f;
        const float4* Rr = reinterpret_cast<const float4*>(rtt) + (size_t)row * NV;
        float4* Or = reinterpret_cast<float4*>(outR) + (size_t)row * NV;
        #pragma unroll 4
        for (int c = threadIdx.x; c < NV; c += 256) {
            float4 rv = __ldcs(Rr + c);
            int4   cu = __ldg(Cr + c);
            float4 o;
            o.x = fmaf(pb, (cu.x > 0) ? 1.f : 0.f, 0.99f * rv.x);
            o.y = fmaf(pb, (cu.y > 0) ? 1.f : 0.f, 0.99f * rv.y);
            o.z = fmaf(pb, (cu.z > 0) ? 1.f : 0.f, 0.99f * rv.z);
            o.w = fmaf(pb, (cu.w > 0) ? 1.f : 0.f, 0.99f * rv.w);
            __stwt(Or + c, o);
        }
    }
}

// First matvec: x1 = b + 0.5*J*b. NO gridsync — independent of k_rtt; runs
// fully concurrent with the rtt stream.
__global__ void __launch_bounds__(128) k_matvec1(const float* __restrict__ J,
                                                 const float* __restrict__ b) {
    cudaTriggerProgrammaticLaunchCompletion();
    int row = blockIdx.x;
    const float4* Jr = reinterpret_cast<const float4*>(J) + (size_t)row * NV;
    const float4* xv = reinterpret_cast<const float4*>(b);
    float s0 = 0.f, s1 = 0.f, s2 = 0.f, s3 = 0.f;
    int c = threadIdx.x;
    #pragma unroll 2
    for (int u = 0; u < 2; u++) {
        float4 a0 = Jr[c],       v0 = xv[c];
        float4 a1 = Jr[c + 128], v1 = xv[c + 128];
        float4 a2 = Jr[c + 256], v2 = xv[c + 256];
        float4 a3 = Jr[c + 384], v3 = xv[c + 384];
        s0 = fmaf(a0.x, v0.x, s0); s0 = fmaf(a0.y, v0.y, s0);
        s0 = fmaf(a0.z, v0.z, s0); s0 = fmaf(a0.w, v0.w, s0);
        s1 = fmaf(a1.x, v1.x, s1); s1 = fmaf(a1.y, v1.y, s1);
        s1 = fmaf(a1.z, v1.z, s1); s1 = fmaf(a1.w, v1.w, s1);
        s2 = fmaf(a2.x, v2.x, s2); s2 = fmaf(a2.y, v2.y, s2);
        s2 = fmaf(a2.z, v2.z, s2); s2 = fmaf(a2.w, v2.w, s2);
        s3 = fmaf(a3.x, v3.x, s3); s3 = fmaf(a3.y, v3.y, s3);
        s3 = fmaf(a3.z, v3.z, s3); s3 = fmaf(a3.w, v3.w, s3);
        c += 512;
    }
    float sum = (s0 + s1) + (s2 + s3);
    #pragma unroll
    for (int o = 16; o; o >>= 1) sum += __shfl_down_sync(0xffffffffu, sum, o);
    __shared__ float s[4];
    if ((threadIdx.x & 31) == 0) s[threadIdx.x >> 5] = sum;
    __syncthreads();
    if (threadIdx.x == 0)
        g_x[1][row] = b[row] + 0.5f * (s[0] + s[1] + s[2] + s[3]);
}

// Warm matvec: y = b + 0.5*J*x, J from L2. Trigger first (lets successor
// prelaunch), then gridsync on the true dependency (previous matvec).
__global__ void __launch_bounds__(128) k_matvec(const float* __restrict__ J,
                                                const float* __restrict__ b, int src) {
    cudaTriggerProgrammaticLaunchCompletion();
    cudaGridDependencySynchronize();
    int row = blockIdx.x;
    const float4* Jr = reinterpret_cast<const float4*>(J) + (size_t)row * NV;
    const float4* xv = reinterpret_cast<const float4*>(g_x[src]);
    float s0 = 0.f, s1 = 0.f;
    int c = threadIdx.x;
    #pragma unroll 4
    for (int u = 0; u < 4; u++) {
        float4 a0 = Jr[c], v0 = xv[c];
        float4 a1 = Jr[c + 128], v1 = xv[c + 128];
        s0 = fmaf(a0.x, v0.x, s0); s0 = fmaf(a0.y, v0.y, s0);
        s0 = fmaf(a0.z, v0.z, s0); s0 = fmaf(a0.w, v0.w, s0);
        s1 = fmaf(a1.x, v1.x, s1); s1 = fmaf(a1.y, v1.y, s1);
        s1 = fmaf(a1.z, v1.z, s1); s1 = fmaf(a1.w, v1.w, s1);
        c += 256;
    }
    float sum = s0 + s1;
    #pragma unroll
    for (int o = 16; o; o >>= 1) sum += __shfl_down_sync(0xffffffffu, sum, o);
    __shared__ float s[4];
    if ((threadIdx.x & 31) == 0) s[threadIdx.x >> 5] = sum;
    __syncthreads();
    if (threadIdx.x == 0)
        g_x[src ^ 1][row] = b[row] + 0.5f * (s[0] + s[1] + s[2] + s[3]);
}

// Per-column coefficients for the J update, computed inline from raw inputs.
// a = 2*x3 - x2 (Richardson / exact Perron cancellation).
__device__ __forceinline__ void col_coef(int j, const float* B_pos,
                                         const int* prev, const float* eta_invs,
                                         float& d, float& p, float& q) {
    float a = 2.f * g_x[1][j] - g_x[0][j];
    float X = fminf(fmaxf(a, 0.f), 1.f);
    float act01 = (X >= 0.99f) ? 1.f : 0.f;
    const float lr_p = 0.1f / 0.12f;
    float Bp = fminf((1.f - lr_p) * B_pos[j] + lr_p * 7.0f * act01, 6.0f);
    Bp = fmaxf(Bp, 0.f);
    float actX = (X < 0.99f) ? 0.f : X;
    int pj = prev[j];
    float ein = (float)pj + 0.99f * eta_invs[j];
    float eta = 1.f / ein;
    if (pj == 1) { d = 1.f - eta; p = eta * 1.008f * Bp; q = eta * 1.008f * actX; }
    else         { d = 1.f;       p = 0.f;               q = 0.f; }
}

// Single post-matvec kernel. Blocks [0,2048): J plasticity update, coeffs
// computed inline (no serialized k_small). Blocks [2048,2064): O(N) outputs.
__global__ void __launch_bounds__(256) k_final(
        const float* __restrict__ J, float* __restrict__ outJ,
        const float* __restrict__ B_pos, const float* __restrict__ B_neg,
        const float* __restrict__ eta_invs, const float* __restrict__ cnt,
        const int* __restrict__ prev, float* __restrict__ out) {
    cudaGridDependencySynchronize();

    if (blockIdx.x >= (NN / RPB) * 4) {
        // ---- O(N) state outputs ----
        int i = (blockIdx.x - (NN / RPB) * 4) * 256 + threadIdx.x;
        const size_t N  = NN;
        const size_t N2 = (size_t)NN * NN;
        float a = 2.f * g_x[1][i] - g_x[0][i];
        out[i] = a;                                   // activity
        float X = fminf(fmaxf(a, 0.f), 1.f);
        float act01 = (X >= 0.99f) ? 1.f : 0.f;
        const float lr_p = 0.1f / 0.12f;
        float Bpn = fminf((1.f - lr_p) * B_pos[i] + lr_p * 7.0f * act01, 6.0f);
        float Bnn = 0.9f * B_neg[i];                  // A_NEG = 0
        float pb = (prev[i] > 0) ? 1.f : 0.f;
        out[N + N2 + i]      = Bpn;                   // B_pos'
        out[2 * N + N2 + i]  = Bnn;                   // B_neg'
        out[3 * N + N2 + i]  = (float)prev[i] + 0.99f * eta_invs[i];  // eta_invs'
        out[4 * N + 2 * N2 + i] = 0.99f * cnt[i] + pb;                // count'
        return;
    }

    // ---- J update ----
    int b = blockIdx.x;
    int jc = b & 3;
    int rowbase = (b >> 2) * RPB;
    int fj = jc * 256 + threadIdx.x;      // float4 index within row
    int j0 = fj << 2;

    float d0, p0, q0, d1, p1, q1, d2, p2, q2, d3, p3, q3;
    col_coef(j0 + 0, B_pos, prev, eta_invs, d0, p0, q0);
    col_coef(j0 + 1, B_pos, prev, eta_invs, d1, p1, q1);
    col_coef(j0 + 2, B_pos, prev, eta_invs, d2, p2, q2);
    col_coef(j0 + 3, B_pos, prev, eta_invs, d3, p3, q3);

    #pragma unroll 4
    for (int r = 0; r < RPB; r++) {
        int i = rowbase + r;
        float ai = 2.f * g_x[1][i] - g_x[0][i];
        float Xi = fminf(fmaxf(ai, 0.f), 1.f);
        float actXi = (Xi < 0.99f) ? 0.f : Xi;
        float Bni = fmaxf(0.9f * B_neg[i], 0.f);

        size_t off = (size_t)i * NV + fj;
        float4 Jv = __ldg(reinterpret_cast<const float4*>(J) + off);

        float jo[4];
        jo[0] = fminf(fmaxf(fmaf(d0, Jv.x, fmaf(actXi, p0, Bni * q0)), 0.f), 1.f);
        jo[1] = fminf(fmaxf(fmaf(d1, Jv.y, fmaf(actXi, p1, Bni * q1)), 0.f), 1.f);
        jo[2] = fminf(fmaxf(fmaf(d2, Jv.z, fmaf(actXi, p2, Bni * q2)), 0.f), 1.f);
        jo[3] = fminf(fmaxf(fmaf(d3, Jv.w, fmaf(actXi, p3, Bni * q3)), 0.f), 1.f);

        if ((i >> 2) == fj) {             // this thread owns the diagonal element
            int jd = i & 3;
            float ja = (jd == 0) ? Jv.x : (jd == 1) ? Jv.y : (jd == 2) ? Jv.z : Jv.w;
            float dd = (jd == 0) ? d0 : (jd == 1) ? d1 : (jd == 2) ? d2 : d3;
            float pp = (jd == 0) ? p0 : (jd == 1) ? p1 : (jd == 2) ? p2 : p3;
            jo[jd] = fminf(fmaxf(fmaf(dd, ja, actXi * pp * (0.165f / 1.008f)), 0.f), 1.f);
        }

        __stcs(reinterpret_cast<float4*>(outJ) + off,
               make_float4(jo[0], jo[1], jo[2], jo[3]));
    }
}

template <typename... Args>
static void launch_pss(void (*kern)(Args...), dim3 grid, dim3 block, Args... args) {
    cudaLaunchConfig_t cfg = {};
    cfg.gridDim = grid;
    cfg.blockDim = block;
    cfg.dynamicSmemBytes = 0;
    cfg.stream = 0;
    cudaLaunchAttribute at[1];
    at[0].id = cudaLaunchAttributeProgrammaticStreamSerialization;
    at[0].val.programmaticStreamSerializationAllowed = 1;
    cfg.attrs = at;
    cfg.numAttrs = 1;
    cudaLaunchKernelEx(&cfg, kern, args...);
}

extern "C" void kernel_launch(void* const* d_in, const int* in_sizes, int n_in,
                              void* d_out, int out_size) {
    const float* inp      = (const float*)d_in[0];
    const float* J        = (const float*)d_in[1];
    const float* B_pos    = (const float*)d_in[2];
    const float* B_neg    = (const float*)d_in[3];
    const float* eta_invs = (const float*)d_in[4];
    const float* rtt      = (const float*)d_in[5];
    const float* cnt      = (const float*)d_in[6];
    const int*   prev     = (const int*)d_in[7];
    const int*   curr     = (const int*)d_in[8];
    float* out = (float*)d_out;

    const size_t N  = NN;
    const size_t N2 = (size_t)NN * NN;
    float* outJ = out + N;
    float* outR = out + 4 * N + N2;

    // rtt DRAM stream (write-through, L2-neutral) overlaps the whole matvec
    // chain via PDL; mv1 has no gridsync (independent of k_rtt).
    k_rtt<<<512, 256>>>(rtt, prev, curr, outR);

    launch_pss(k_matvec1, dim3(NN), dim3(128), J, inp);
    launch_pss(k_matvec,  dim3(NN), dim3(128), J, inp, 1);
    launch_pss(k_matvec,  dim3(NN), dim3(128), J, inp, 0);
    launch_pss(k_final,   dim3((NN / RPB) * 4 + NN / 256), dim3(256),
               J, outJ, B_pos, B_neg, eta_invs, cnt, prev, out);
}